// round 10
// baseline (speedup 1.0000x reference)
#include <cuda_runtime.h>
#include <math.h>

#define N_Q   10
#define NB    10
#define DIM   1024
#define P     128
#define FEAT  (NB * N_Q)
#define NBLK  128
#define NT    1024

typedef unsigned long long ull;

// ---------------- scratch (device globals) ----------------
__device__ float2   g_psi[P * DIM];          // [pt][d] amplitudes (16B-aligned pairs)
__device__ float    g_part[NBLK * 2];
__device__ unsigned g_bar  = 0;              // monotonic grid barrier
__device__ unsigned g_tick = 0;              // monotonic finish ticket

// packed f32x2 helpers (gram accumulators) ----------------------------------
__device__ __forceinline__ ull pk(float lo, float hi) {
    ull r; asm("mov.b64 %0, {%1,%2};" : "=l"(r) : "f"(lo), "f"(hi)); return r;
}
__device__ __forceinline__ void upk(ull v, float& lo, float& hi) {
    asm("mov.b64 {%0,%1}, %2;" : "=f"(lo), "=f"(hi) : "l"(v));
}
__device__ __forceinline__ void fma2acc(ull& acc, ull a, ull b) {
    asm("fma.rn.f32x2 %0, %1, %2, %0;" : "+l"(acc) : "l"(a), "l"(b));
}
__device__ __forceinline__ void add2acc(ull& acc, ull v) {
    asm("add.rn.f32x2 %0, %0, %1;" : "+l"(acc) : "l"(v));
}

// monotonic grid barrier (replay-safe)
__device__ __forceinline__ void grid_sync() {
    __syncthreads();
    __threadfence();
    if (threadIdx.x == 0) {
        unsigned old = atomicAdd(&g_bar, 1u);
        unsigned target = (old / NBLK + 1u) * NBLK;
        unsigned cur;
        do {
            asm volatile("ld.acquire.gpu.u32 %0, [%1];" : "=r"(cur) : "l"(&g_bar));
        } while (cur < target);
    }
    __syncthreads();
    __threadfence();
}

// single-amplitude complex 2x2 butterfly via lane shuffle
__device__ __forceinline__ void bfly1(float2& a, int m, const float* U8, int bit)
{
    float px = __shfl_xor_sync(0xffffffffu, a.x, m);
    float py = __shfl_xor_sync(0xffffffffu, a.y, m);
    float4 cf = *(const float4*)(U8 + (bit ? 4 : 0));   // (cu.x,cu.y,cv.x,cv.y)
    float nx = fmaf(cf.x, a.x, fmaf(-cf.y, a.y, fmaf(cf.z, px, -cf.w * py)));
    float ny = fmaf(cf.x, a.y, fmaf( cf.y, a.x, fmaf(cf.z, py,  cf.w * px)));
    a = make_float2(nx, ny);
}

// ---------------------------------------------------------------------------
__global__ __launch_bounds__(NT, 1)
void fused_kernel(const float* __restrict__ data,
                  const float* __restrict__ labels,
                  const float* __restrict__ params,
                  float* __restrict__ out)
{
    __shared__ float4 pool[2048];                 // 32 KB: transpose / gram staging
    __shared__ float  Umat[NB * N_Q * 8];         // folded U = RY*RZ*H per (blk,q)
    __shared__ float  crz[NB * N_Q];
    __shared__ float  red1[32], red2[32], red3[32];
    __shared__ int    s_win;

    const int t    = threadIdx.x;                 // 0..1023
    const int pt   = blockIdx.x;
    const int lane = t & 31;
    const int W    = t >> 5;                      // warp id (= t bits 5..9)

    // phase-A basis index: dA = t. phase-B: dB = swap bits [9:5]<->[4:0]
    const int dB = ((t & 31) << 5) | ((t >> 5) & 31);
    // transpose smem slots (float2, XOR swizzle; both directions conflict-free)
    const int widx = t ^ (W & 31);                           // store own amp
    const int ridx = dB ^ ((dB >> 5) & 31);                  // fetch partner slot

    // ---- init: folded U matrices + CRZ angles ----
    if (t < NB * N_Q) {
        int b = t / N_Q, q = t % N_Q;
        float th    = data[pt * FEAT + b * N_Q + q];
        float theta = params[(b * 2 + 0) * N_Q + q];
        float c, s;   __sincosf(0.5f * theta, &s, &c);
        float st, ct; __sincosf(0.5f * th, &st, &ct);
        const float iv = 0.70710678118654752440f;
        float cps = (c + s) * iv, cms = (c - s) * iv;
        float* Up = &Umat[t * 8];
        Up[0] =  cms * ct; Up[1] = -cps * st;     // u00
        Up[2] =  cps * ct; Up[3] = -cms * st;     // u01
        Up[4] = -cms * ct; Up[5] = -cps * st;     // u11
        Up[6] =  cps * ct; Up[7] =  cms * st;     // u10
        crz[t] = params[(b * 2 + 1) * N_Q + q];
    }
    __syncthreads();

    // ====================== PHASE 1: state prep ======================
    {
        float2 a;
        float2* xb = (float2*)pool;               // two 1024-float2 buffers
        int tb = 0;

        // CRZ ring diagonal for own amplitude index d
        auto crzApply = [&](int blk, int d) {
            float ang = 0.0f;
            #pragma unroll
            for (int q = 0; q < N_Q; q++) {
                int pA = N_Q - 1 - q;
                int pB = (q == N_Q - 1) ? (N_Q - 1) : (N_Q - 2 - q);
                if ((d >> pA) & 1)
                    ang += (((d >> pB) & 1) ? 0.5f : -0.5f) * crz[blk * N_Q + q];
            }
            float sn, cs; __sincosf(ang, &sn, &cs);
            a = make_float2(a.x * cs - a.y * sn, a.x * sn + a.y * cs);
        };

        auto transpose = [&]() {
            float2* buf = xb + tb * 1024;
            __syncthreads();                      // protect vs previous readers
            buf[widx] = a;
            __syncthreads();
            a = buf[ridx];
            tb ^= 1;
        };

        // lane-resident butterflies. Phase A: qubits 9..5; phase B: qubits 4..0
        auto bflyA = [&](const float* Ub) {
            #pragma unroll
            for (int k = 0; k < 5; k++)
                bfly1(a, 1 << k, Ub + (9 - k) * 8, (lane >> k) & 1);
        };
        auto bflyB = [&](const float* Ub) {
            #pragma unroll
            for (int k = 0; k < 5; k++)
                bfly1(a, 1 << k, Ub + (4 - k) * 8, (lane >> k) & 1);
        };

        // ---- block 0: product state directly in phase-B ownership ----
        {
            float px = 1.0f, py = 0.0f;
            #pragma unroll
            for (int q = 0; q < N_Q; q++) {
                int bit = (dB >> (N_Q - 1 - q)) & 1;
                const float* Up = &Umat[q * 8] + (bit ? 6 : 0);   // u10 : u00
                float ux = Up[0], uy = Up[1];
                float nx = px * ux - py * uy;
                float ny = px * uy + py * ux;
                px = nx; py = ny;
            }
            a = make_float2(px, py);
            crzApply(0, dB);
        }

        // blocks 1..9 alternate: B->A (odd), A->B (even)
        #pragma unroll
        for (int blk = 1; blk < NB; blk++) {
            const float* Ub = &Umat[blk * N_Q * 8];
            if (blk & 1) {          // state in B: qubits 4..0, transpose, 9..5, CRZ(A)
                bflyB(Ub);
                transpose();        // -> A
                bflyA(Ub);
                crzApply(blk, t);
            } else {                // state in A: qubits 9..5, transpose, 4..0, CRZ(B)
                bflyA(Ub);
                transpose();        // -> B
                bflyB(Ub);
                crzApply(blk, dB);
            }
        }
        // ends in phase A: d = t
        g_psi[pt * DIM + t] = a;
    }

    grid_sync();

    // ====================== PHASE 2: balanced symmetric Gram ======================
    {
        const float4* psi4 = (const float4*)g_psi;   // [pt][dp] pairs
        const int u_sel = t >> 9;                    // staging: A/B half
        const int u_r   = (t >> 6) & 7;              // staging row
        const int u_dp  = t & 63;                    // staging dp-local
        const int ks    = t >> 6;                    // split-K group (0..15)
        const int ii    = t & 7;
        const int jj    = (t >> 3) & 7;

        int grp1, grp2, gii, gjj, op1, op2;
        float w;
        if (blockIdx.x < 120) {                      // off-diagonal tile (I < J)
            int I = 0, rem = blockIdx.x;
            while (rem >= 15 - I) { rem -= 15 - I; I++; }
            grp1 = I; grp2 = I + 1 + rem;
            gii = ii; gjj = jj;
            op1 = 0; op2 = 1; w = 2.0f;
        } else {                                     // two diagonal tiles packed
            int v = blockIdx.x - 120;
            grp1 = 2 * v; grp2 = 2 * v + 1;
            int slot = t & 63;
            if (slot < 56) {
                int sel = (slot >= 28);
                int p = slot - (sel ? 28 : 0);
                int r = 0;
                while (p >= 7 - r) { p -= 7 - r; r++; }
                gii = r; gjj = r + 1 + p;            // strict upper triangle
                op1 = op2 = sel; w = 2.0f;
            } else { gii = 0; gjj = 0; op1 = op2 = 0; w = 0.0f; }
        }
        const int gi = (op1 ? grp2 : grp1) * 8 + gii;
        const int gj = (op2 ? grp2 : grp1) * 8 + gjj;
        const int ldrow = ((u_sel ? grp2 : grp1) * 8 + u_r) * 512;

        ull accp = 0ull, accm = 0ull;

        // prologue: stage chunk 0 (one float4 per thread)
        float4 r0 = __ldg(&psi4[ldrow + u_dp]);
        __syncthreads();
        pool[u_sel * 512 + u_dp * 8 + (u_r ^ (u_dp & 7))] = r0;
        __syncthreads();

        #pragma unroll
        for (int c = 0; c < 8; c++) {
            const float4* base = pool + (c & 1) * 1024;
            const float4* s1 = base + op1 * 512;
            const float4* s2 = base + op2 * 512;
            if (c < 7)
                r0 = __ldg(&psi4[ldrow + (c + 1) * 64 + u_dp]);
            #pragma unroll
            for (int it = 0; it < 4; it++) {
                int dpl = ks * 4 + it;
                int k0  = dpl & 7;
                float4 A = s1[dpl * 8 + (gii ^ k0)];
                float4 B = s2[dpl * 8 + (gjj ^ k0)];
                fma2acc(accp, pk(A.x, A.y), pk(B.x, B.y));
                fma2acc(accm, pk(A.x, A.y), pk(B.y, B.x));
                fma2acc(accp, pk(A.z, A.w), pk(B.z, B.w));
                fma2acc(accm, pk(A.z, A.w), pk(B.w, B.z));
            }
            if (c < 7)
                pool[((c + 1) & 1) * 1024 + u_sel * 512 + u_dp * 8 + (u_r ^ (u_dp & 7))] = r0;
            __syncthreads();
        }

        // cross-ks reduction (16 groups)
        ull* sbuf = (ull*)pool;
        sbuf[t * 2 + 0] = accp;
        sbuf[t * 2 + 1] = accm;
        __syncthreads();

        float v1 = 0.0f, v2 = 0.0f;
        if (ks == 0) {                               // t < 64
            #pragma unroll
            for (int g = 1; g < 16; g++) {
                add2acc(accp, sbuf[(g * 64 + t) * 2 + 0]);
                add2acc(accm, sbuf[(g * 64 + t) * 2 + 1]);
            }
            float pxx, pyy, mxy, myx;
            upk(accp, pxx, pyy);
            upk(accm, mxy, myx);
            float re = pxx + pyy;
            float im = myx - mxy;
            float K  = re * re + im * im;
            v1 = w * labels[gi] * labels[gj] * K;
            v2 = w * K * K;
        }

        #pragma unroll
        for (int o = 16; o; o >>= 1) {
            v1 += __shfl_down_sync(0xffffffffu, v1, o);
            v2 += __shfl_down_sync(0xffffffffu, v2, o);
        }
        if (lane == 0) { red1[W] = v1; red2[W] = v2; }
        __syncthreads();
        if (t < 32) {
            v1 = red1[t]; v2 = red2[t];
            #pragma unroll
            for (int o = 16; o; o >>= 1) {
                v1 += __shfl_down_sync(0xffffffffu, v1, o);
                v2 += __shfl_down_sync(0xffffffffu, v2, o);
            }
            if (t == 0) {
                g_part[blockIdx.x * 2 + 0] = v1;
                g_part[blockIdx.x * 2 + 1] = v2;
            }
        }
    }

    // ====================== PHASE 3: last-block final ======================
    if (t == 0) {
        __threadfence();
        unsigned old = atomicAdd(&g_tick, 1u);
        s_win = ((old % NBLK) == (NBLK - 1)) ? 1 : 0;
    }
    __syncthreads();

    if (s_win) {
        __threadfence();
        volatile float* vp = (volatile float*)g_part;
        float pol = 0.0f, k2 = 0.0f, l2 = 0.0f;
        if (t < NBLK) { pol = vp[2 * t]; k2 = vp[2 * t + 1]; }
        if (t < P) {
            float l = labels[t];
            l2 = l * l;
            pol += l2;                               // analytic diagonal K[i,i]=1
            k2  += 1.0f;
        }
        #pragma unroll
        for (int o = 16; o; o >>= 1) {
            pol += __shfl_down_sync(0xffffffffu, pol, o);
            k2  += __shfl_down_sync(0xffffffffu, k2, o);
            l2  += __shfl_down_sync(0xffffffffu, l2, o);
        }
        if (lane == 0) { red1[W] = pol; red2[W] = k2; red3[W] = l2; }
        __syncthreads();
        if (t == 0) {
            float POL = 0.0f, K2 = 0.0f, SL = 0.0f;
            #pragma unroll
            for (int wv = 0; wv < 32; wv++) {
                POL += red1[wv]; K2 += red2[wv]; SL += red3[wv];
            }
            out[0] = POL / (sqrtf(K2) * SL);
        }
    }
}

// ---------------------------------------------------------------------------
extern "C" void kernel_launch(void* const* d_in, const int* in_sizes, int n_in,
                              void* d_out, int out_size)
{
    const float* data   = (const float*)d_in[0];   // [128, 100]
    const float* labels = (const float*)d_in[1];   // [128]
    const float* params = (const float*)d_in[2];   // [10, 2, 10]
    float* out = (float*)d_out;

    fused_kernel<<<NBLK, NT>>>(data, labels, params, out);
}

// round 11
// speedup vs baseline: 1.0827x; 1.0827x over previous
#include <cuda_runtime.h>
#include <math.h>

#define N_Q   10
#define NB    10
#define DIM   1024
#define P     128
#define FEAT  (NB * N_Q)
#define NBLK  128

typedef unsigned long long ull;

// ---------------- scratch (device globals) ----------------
__device__ float4   g_psi[P * (DIM / 2)];    // [pt][dp] : dims (2dp, 2dp+1)
__device__ float    g_part[NBLK * 2];
__device__ unsigned g_launch = 0;            // launch-epoch ticket (monotonic)
__device__ unsigned g_grp[16];               // per-point-group ready counters (monotonic)
__device__ unsigned g_tick = 0;              // finish ticket (monotonic)

// packed f32x2 helpers (gram accumulators) ----------------------------------
__device__ __forceinline__ ull pk(float lo, float hi) {
    ull r; asm("mov.b64 %0, {%1,%2};" : "=l"(r) : "f"(lo), "f"(hi)); return r;
}
__device__ __forceinline__ void upk(ull v, float& lo, float& hi) {
    asm("mov.b64 {%0,%1}, %2;" : "=f"(lo), "=f"(hi) : "l"(v));
}
__device__ __forceinline__ void fma2acc(ull& acc, ull a, ull b) {
    asm("fma.rn.f32x2 %0, %1, %2, %0;" : "+l"(acc) : "l"(a), "l"(b));
}
__device__ __forceinline__ void add2acc(ull& acc, ull v) {
    asm("add.rn.f32x2 %0, %0, %1;" : "+l"(acc) : "l"(v));
}

// general complex-2x2 shuffle butterfly: own' = cu*own + cv*partner
__device__ __forceinline__ void bfly(float2& a0, float2& a1, int m,
                                     const float* U8, int bit)
{
    float p0x = __shfl_xor_sync(0xffffffffu, a0.x, m);
    float p0y = __shfl_xor_sync(0xffffffffu, a0.y, m);
    float p1x = __shfl_xor_sync(0xffffffffu, a1.x, m);
    float p1y = __shfl_xor_sync(0xffffffffu, a1.y, m);
    float4 cf = *(const float4*)(U8 + (bit ? 4 : 0));  // (cu.x,cu.y,cv.x,cv.y)
    float n0x = fmaf(cf.x, a0.x, fmaf(-cf.y, a0.y, fmaf(cf.z, p0x, -cf.w * p0y)));
    float n0y = fmaf(cf.x, a0.y, fmaf( cf.y, a0.x, fmaf(cf.z, p0y,  cf.w * p0x)));
    float n1x = fmaf(cf.x, a1.x, fmaf(-cf.y, a1.y, fmaf(cf.z, p1x, -cf.w * p1y)));
    float n1y = fmaf(cf.x, a1.y, fmaf( cf.y, a1.x, fmaf(cf.z, p1y,  cf.w * p1x)));
    a0 = make_float2(n0x, n0y); a1 = make_float2(n1x, n1y);
}

// register-local butterfly on d-bit0 (qubit 9)
__device__ __forceinline__ void bflyLocal(float2& a0, float2& a1, const float* U8)
{
    float4 lo = *(const float4*)(U8);      // (u00, u01)
    float4 hi = *(const float4*)(U8 + 4);  // (u11, u10)
    float n0x = fmaf(lo.x, a0.x, fmaf(-lo.y, a0.y, fmaf(lo.z, a1.x, -lo.w * a1.y)));
    float n0y = fmaf(lo.x, a0.y, fmaf( lo.y, a0.x, fmaf(lo.z, a1.y,  lo.w * a1.x)));
    float n1x = fmaf(hi.z, a0.x, fmaf(-hi.w, a0.y, fmaf(hi.x, a1.x, -hi.y * a1.y)));
    float n1y = fmaf(hi.z, a0.y, fmaf( hi.w, a0.x, fmaf(hi.x, a1.y,  hi.y * a1.x)));
    a0 = make_float2(n0x, n0y); a1 = make_float2(n1x, n1y);
}

// ---------------------------------------------------------------------------
__global__ __launch_bounds__(512, 1)
void fused_kernel(const float* __restrict__ data,
                  const float* __restrict__ labels,
                  const float* __restrict__ params,
                  float* __restrict__ out)
{
    __shared__ float4 pool[2048];                 // 32 KB: transpose / gram staging
    __shared__ float  Umat[NB * N_Q * 8];         // folded U = RY*RZ*H per (blk,q)
    __shared__ float  crz[NB * N_Q];
    __shared__ float  tCZc[NB * 4], tCZs[NB * 4]; // CRZ odd-d delta sincos
    __shared__ float  red1[16], red2[16], red3[16];
    __shared__ unsigned s_epoch;
    __shared__ int    s_win;

    const int t  = threadIdx.x;
    const int pt = blockIdx.x;

    // ownership transpose: swap t bits [8:5] <-> [3:0], keep bit 4
    const int swp  = (t & 0x10) | ((t & 0xF) << 5) | ((t >> 5) & 0xF);
    const int widx = t   ^ ((t   >> 5) & 0xF);
    const int ridx = swp ^ ((swp >> 5) & 0xF);
    const int dA0 = 2 * t;
    const int dB0 = 2 * swp;
    const int czA = (((dA0 >> 9) & 1) << 1) | ((dA0 >> 1) & 1);
    const int czB = (((dB0 >> 9) & 1) << 1) | ((dB0 >> 1) & 1);

    // ---- launch epoch (replay-safe: launches are stream-ordered) ----
    if (t == 0) s_epoch = atomicAdd(&g_launch, 1u) / NBLK;

    // ---- init: folded U matrices (per point) + CRZ tables ----
    if (t < NB * N_Q) {
        int b = t / N_Q, q = t % N_Q;
        float th    = data[pt * FEAT + b * N_Q + q];
        float theta = params[(b * 2 + 0) * N_Q + q];
        float c, s;   __sincosf(0.5f * theta, &s, &c);
        float st, ct; __sincosf(0.5f * th, &st, &ct);
        const float iv = 0.70710678118654752440f;
        float cps = (c + s) * iv, cms = (c - s) * iv;
        float* Up = &Umat[t * 8];
        Up[0] =  cms * ct; Up[1] = -cps * st;    // u00
        Up[2] =  cps * ct; Up[3] = -cms * st;    // u01
        Up[4] = -cms * ct; Up[5] = -cps * st;    // u11
        Up[6] =  cps * ct; Up[7] =  cms * st;    // u10
        crz[t] = params[(b * 2 + 1) * N_Q + q];
    }
    if (t >= 256 && t < 256 + NB * 4) {
        int u = t - 256, b = u >> 2, idx = u & 3;
        float cz9 = params[(b * 2 + 1) * N_Q + 9];
        float cz8 = params[(b * 2 + 1) * N_Q + 8];
        float delta = ((idx & 2) ? 0.5f : -0.5f) * cz9 + ((idx & 1) ? cz8 : 0.0f);
        float sn, cs; __sincosf(delta, &sn, &cs);
        tCZc[u] = cs; tCZs[u] = sn;
    }
    __syncthreads();
    const unsigned epoch = s_epoch;

    // ====================== PHASE 1: state prep ======================
    {
        float2 a0, a1;
        int tb = 0;

        auto crzApply = [&](int blk, int d0, int czidx) {
            float ang = 0.0f;
            #pragma unroll
            for (int q = 0; q < N_Q; q++) {
                int pA = N_Q - 1 - q;
                int pB = (q == N_Q - 1) ? (N_Q - 1) : (N_Q - 2 - q);
                if ((d0 >> pA) & 1)
                    ang += (((d0 >> pB) & 1) ? 0.5f : -0.5f) * crz[blk * N_Q + q];
            }
            float s0, c0; __sincosf(ang, &s0, &c0);
            float cD = tCZc[blk * 4 + czidx], sD = tCZs[blk * 4 + czidx];
            float s1 = s0 * cD + c0 * sD;
            float c1 = c0 * cD - s0 * sD;
            float2 n0 = make_float2(a0.x * c0 - a0.y * s0, a0.x * s0 + a0.y * c0);
            float2 n1 = make_float2(a1.x * c1 - a1.y * s1, a1.x * s1 + a1.y * c1);
            a0 = n0; a1 = n1;
        };

        // single-sync transpose: write buf[tb], sync, read. Safe with 2 buffers.
        auto transpose = [&]() {
            float4* buf = pool + tb * 512;
            buf[widx] = make_float4(a0.x, a0.y, a1.x, a1.y);
            __syncthreads();
            float4 v = buf[ridx];
            a0 = make_float2(v.x, v.y);
            a1 = make_float2(v.z, v.w);
            tb ^= 1;
        };

        // state in A: apply 10 qubit-U's + CRZ; ends in B
        auto oddPattern = [&](int blk) {
            const float* Ub = &Umat[blk * N_Q * 8];
            bflyLocal(a0, a1, Ub + 9 * 8);                       // q9 (d bit0)
            #pragma unroll
            for (int k = 0; k < 5; k++)                          // q8..q4 (d bits1-5)
                bfly(a0, a1, 1 << k, Ub + (8 - k) * 8, (t >> k) & 1);
            transpose();                                         // A -> B
            #pragma unroll
            for (int k = 0; k < 4; k++)                          // q3..q0 (d bits6-9)
                bfly(a0, a1, 1 << k, Ub + (3 - k) * 8, (t >> k) & 1);
            crzApply(blk, dB0, czB);
        };

        // state in B: ends in A
        auto evenPattern = [&](int blk) {
            const float* Ub = &Umat[blk * N_Q * 8];
            bflyLocal(a0, a1, Ub + 9 * 8);                       // q9
            #pragma unroll
            for (int k = 0; k < 4; k++)                          // q3..q0
                bfly(a0, a1, 1 << k, Ub + (3 - k) * 8, (t >> k) & 1);
            bfly(a0, a1, 16, Ub + 4 * 8, (t >> 4) & 1);          // q4 (d bit5)
            transpose();                                         // B -> A
            #pragma unroll
            for (int k = 0; k < 4; k++)                          // q8..q5 (d bits1-4)
                bfly(a0, a1, 1 << k, Ub + (8 - k) * 8, (t >> k) & 1);
            crzApply(blk, dA0, czA);
        };

        // ---- block 0 of circuit: product state directly in B ownership ----
        {
            float px = 1.0f, py = 0.0f;
            #pragma unroll
            for (int q = 0; q < 9; q++) {                        // q0..q8 <-> d bits 9..1
                int bit = (dB0 >> (N_Q - 1 - q)) & 1;
                const float* Up = &Umat[q * 8] + (bit ? 6 : 0);  // u10 : u00
                float ux = Up[0], uy = Up[1];
                float nx = px * ux - py * uy;
                float ny = px * uy + py * ux;
                px = nx; py = ny;
            }
            const float* U9 = &Umat[9 * 8];
            a0 = make_float2(px * U9[0] - py * U9[1], px * U9[1] + py * U9[0]); // u00
            a1 = make_float2(px * U9[6] - py * U9[7], px * U9[7] + py * U9[6]); // u10
            crzApply(0, dB0, czB);
        }

        #pragma unroll
        for (int pr = 0; pr < 4; pr++) {
            evenPattern(2 * pr + 1);
            oddPattern(2 * pr + 2);
        }
        evenPattern(9);                                          // ends in A

        g_psi[pt * (DIM / 2) + t] = make_float4(a0.x, a0.y, a1.x, a1.y);
    }

    // ---- publish: this point's group gains one arrival ----
    __threadfence();
    __syncthreads();
    if (t == 0) atomicAdd(&g_grp[pt >> 3], 1u);

    // ====================== PHASE 2: balanced symmetric Gram ======================
    {
        const int u_r  = t >> 6;          // staging row (0..7)
        const int u_dp = t & 63;          // staging dp-local
        const int ks   = t >> 6;          // split-K group

        int grp1, grp2, ii, jj, op1, op2;
        float w;
        if (blockIdx.x < 120) {           // off-diagonal tile (I < J)
            int I = 0, rem = blockIdx.x;
            while (rem >= 15 - I) { rem -= 15 - I; I++; }
            grp1 = I; grp2 = I + 1 + rem;
            ii = t & 7; jj = (t >> 3) & 7;
            op1 = 0; op2 = 1; w = 2.0f;
        } else {                          // two diagonal tiles packed in one block
            int v = blockIdx.x - 120;
            grp1 = 2 * v; grp2 = 2 * v + 1;
            int slot = t & 63;
            if (slot < 56) {
                int sel = (slot >= 28);
                int p = slot - (sel ? 28 : 0);
                int r = 0;
                while (p >= 7 - r) { p -= 7 - r; r++; }
                ii = r; jj = r + 1 + p;   // strict upper triangle
                op1 = op2 = sel; w = 2.0f;
            } else { ii = 0; jj = 0; op1 = op2 = 0; w = 0.0f; }
        }
        const int gi = (op1 ? grp2 : grp1) * 8 + ii;
        const int gj = (op2 ? grp2 : grp1) * 8 + jj;

        // ---- wait only for the two needed point-groups ----
        if (t == 0) {
            const unsigned tgt = 8u * (epoch + 1u);
            unsigned c;
            do { asm volatile("ld.acquire.gpu.u32 %0, [%1];" : "=r"(c) : "l"(&g_grp[grp1])); } while (c < tgt);
            do { asm volatile("ld.acquire.gpu.u32 %0, [%1];" : "=r"(c) : "l"(&g_grp[grp2])); } while (c < tgt);
        }
        __syncthreads();
        __threadfence();

        ull accp = 0ull, accm = 0ull;

        // prologue: stage chunk 0
        float4 rA = __ldg(&g_psi[(grp1 * 8 + u_r) * (DIM / 2) + u_dp]);
        float4 rB = __ldg(&g_psi[(grp2 * 8 + u_r) * (DIM / 2) + u_dp]);
        __syncthreads();                   // prep's last transpose reads are done
        pool[      u_dp * 8 + (u_r ^ (u_dp & 7))] = rA;
        pool[512 + u_dp * 8 + (u_r ^ (u_dp & 7))] = rB;
        __syncthreads();

        #pragma unroll
        for (int c = 0; c < 8; c++) {
            const float4* base = pool + (c & 1) * 1024;
            const float4* s1 = base + op1 * 512;
            const float4* s2 = base + op2 * 512;
            if (c < 7) {
                rA = __ldg(&g_psi[(grp1 * 8 + u_r) * (DIM / 2) + (c + 1) * 64 + u_dp]);
                rB = __ldg(&g_psi[(grp2 * 8 + u_r) * (DIM / 2) + (c + 1) * 64 + u_dp]);
            }
            #pragma unroll
            for (int it = 0; it < 8; it++) {
                int dpl = ks * 8 + it;
                int k0  = dpl & 7;
                float4 A = s1[dpl * 8 + (ii ^ k0)];
                float4 B = s2[dpl * 8 + (jj ^ k0)];
                fma2acc(accp, pk(A.x, A.y), pk(B.x, B.y));
                fma2acc(accm, pk(A.x, A.y), pk(B.y, B.x));
                fma2acc(accp, pk(A.z, A.w), pk(B.z, B.w));
                fma2acc(accm, pk(A.z, A.w), pk(B.w, B.z));
            }
            if (c < 7) {
                float4* dst = pool + ((c + 1) & 1) * 1024;
                dst[      u_dp * 8 + (u_r ^ (u_dp & 7))] = rA;
                dst[512 + u_dp * 8 + (u_r ^ (u_dp & 7))] = rB;
            }
            __syncthreads();
        }

        // cross-ks reduction
        ull* sbuf = (ull*)pool;
        sbuf[t * 2 + 0] = accp;
        sbuf[t * 2 + 1] = accm;
        __syncthreads();

        float v1 = 0.0f, v2 = 0.0f;
        if (ks == 0) {
            #pragma unroll
            for (int g = 1; g < 8; g++) {
                add2acc(accp, sbuf[(g * 64 + t) * 2 + 0]);
                add2acc(accm, sbuf[(g * 64 + t) * 2 + 1]);
            }
            float pxx, pyy, mxy, myx;
            upk(accp, pxx, pyy);
            upk(accm, mxy, myx);
            float re = pxx + pyy;
            float im = myx - mxy;
            float K  = re * re + im * im;
            v1 = w * labels[gi] * labels[gj] * K;
            v2 = w * K * K;
        }

        #pragma unroll
        for (int o = 16; o; o >>= 1) {
            v1 += __shfl_down_sync(0xffffffffu, v1, o);
            v2 += __shfl_down_sync(0xffffffffu, v2, o);
        }
        const int warp = t >> 5, lanei = t & 31;
        if (lanei == 0) { red1[warp] = v1; red2[warp] = v2; }
        __syncthreads();
        if (t < 16) {
            v1 = red1[t]; v2 = red2[t];
            #pragma unroll
            for (int o = 8; o; o >>= 1) {
                v1 += __shfl_down_sync(0xffffu, v1, o);
                v2 += __shfl_down_sync(0xffffu, v2, o);
            }
            if (t == 0) {
                g_part[blockIdx.x * 2 + 0] = v1;
                g_part[blockIdx.x * 2 + 1] = v2;
            }
        }
    }

    // ====================== PHASE 3: last-block final ======================
    if (t == 0) {
        __threadfence();
        unsigned old = atomicAdd(&g_tick, 1u);
        s_win = ((old % NBLK) == (NBLK - 1)) ? 1 : 0;
    }
    __syncthreads();

    if (s_win) {
        __threadfence();
        volatile float* vp = (volatile float*)g_part;
        float pol = 0.0f, k2 = 0.0f, l2 = 0.0f;
        if (t < NBLK) { pol = vp[2 * t]; k2 = vp[2 * t + 1]; }
        if (t < P) {
            float l = labels[t];
            l2 = l * l;
            pol += l2;                      // analytic diagonal K[i,i]=1
            k2  += 1.0f;
        }
        #pragma unroll
        for (int o = 16; o; o >>= 1) {
            pol += __shfl_down_sync(0xffffffffu, pol, o);
            k2  += __shfl_down_sync(0xffffffffu, k2, o);
            l2  += __shfl_down_sync(0xffffffffu, l2, o);
        }
        const int warp = t >> 5, lanei = t & 31;
        if (lanei == 0) { red1[warp] = pol; red2[warp] = k2; red3[warp] = l2; }
        __syncthreads();
        if (t == 0) {
            float POL = 0.0f, K2 = 0.0f, SL = 0.0f;
            #pragma unroll
            for (int wv = 0; wv < 16; wv++) {
                POL += red1[wv]; K2 += red2[wv]; SL += red3[wv];
            }
            out[0] = POL / (sqrtf(K2) * SL);
        }
    }
}

// ---------------------------------------------------------------------------
extern "C" void kernel_launch(void* const* d_in, const int* in_sizes, int n_in,
                              void* d_out, int out_size)
{
    const float* data   = (const float*)d_in[0];   // [128, 100]
    const float* labels = (const float*)d_in[1];   // [128]
    const float* params = (const float*)d_in[2];   // [10, 2, 10]
    float* out = (float*)d_out;

    fused_kernel<<<NBLK, 512>>>(data, labels, params, out);
}

// round 13
// speedup vs baseline: 1.0992x; 1.0153x over previous
#include <cuda_runtime.h>
#include <math.h>

#define N_Q   10
#define NB    10
#define DIM   1024
#define P     128
#define FEAT  (NB * N_Q)
#define NBLK  128

typedef unsigned long long ull;

// ---------------- scratch (device globals) ----------------
__device__ float4   g_psi[P * (DIM / 2)];    // [pt][dp] : dims (2dp, 2dp+1)
__device__ float    g_part[NBLK * 2];
__device__ unsigned g_launch = 0;            // launch-epoch ticket (monotonic)
__device__ unsigned g_grp[16];               // per-point-group ready counters (monotonic)
__device__ unsigned g_tick = 0;              // finish ticket (monotonic)

// packed f32x2 helpers (gram accumulators) ----------------------------------
__device__ __forceinline__ ull pk(float lo, float hi) {
    ull r; asm("mov.b64 %0, {%1,%2};" : "=l"(r) : "f"(lo), "f"(hi)); return r;
}
__device__ __forceinline__ void upk(ull v, float& lo, float& hi) {
    asm("mov.b64 {%0,%1}, %2;" : "=f"(lo), "=f"(hi) : "l"(v));
}
__device__ __forceinline__ void fma2acc(ull& acc, ull a, ull b) {
    asm("fma.rn.f32x2 %0, %1, %2, %0;" : "+l"(acc) : "l"(a), "l"(b));
}
__device__ __forceinline__ void add2acc(ull& acc, ull v) {
    asm("add.rn.f32x2 %0, %0, %1;" : "+l"(acc) : "l"(v));
}

// general complex-2x2 shuffle butterfly: own' = cu*own + cv*partner
__device__ __forceinline__ void bfly(float2& a0, float2& a1, int m,
                                     const float* U8, int bit)
{
    float p0x = __shfl_xor_sync(0xffffffffu, a0.x, m);
    float p0y = __shfl_xor_sync(0xffffffffu, a0.y, m);
    float p1x = __shfl_xor_sync(0xffffffffu, a1.x, m);
    float p1y = __shfl_xor_sync(0xffffffffu, a1.y, m);
    float4 cf = *(const float4*)(U8 + (bit ? 4 : 0));  // (cu.x,cu.y,cv.x,cv.y)
    float n0x = fmaf(cf.x, a0.x, fmaf(-cf.y, a0.y, fmaf(cf.z, p0x, -cf.w * p0y)));
    float n0y = fmaf(cf.x, a0.y, fmaf( cf.y, a0.x, fmaf(cf.z, p0y,  cf.w * p0x)));
    float n1x = fmaf(cf.x, a1.x, fmaf(-cf.y, a1.y, fmaf(cf.z, p1x, -cf.w * p1y)));
    float n1y = fmaf(cf.x, a1.y, fmaf( cf.y, a1.x, fmaf(cf.z, p1y,  cf.w * p1x)));
    a0 = make_float2(n0x, n0y); a1 = make_float2(n1x, n1y);
}

// register-local butterfly on d-bit0 (qubit 9)
__device__ __forceinline__ void bflyLocal(float2& a0, float2& a1, const float* U8)
{
    float4 lo = *(const float4*)(U8);      // (u00, u01)
    float4 hi = *(const float4*)(U8 + 4);  // (u11, u10)
    float n0x = fmaf(lo.x, a0.x, fmaf(-lo.y, a0.y, fmaf(lo.z, a1.x, -lo.w * a1.y)));
    float n0y = fmaf(lo.x, a0.y, fmaf( lo.y, a0.x, fmaf(lo.z, a1.y,  lo.w * a1.x)));
    float n1x = fmaf(hi.z, a0.x, fmaf(-hi.w, a0.y, fmaf(hi.x, a1.x, -hi.y * a1.y)));
    float n1y = fmaf(hi.z, a0.y, fmaf( hi.w, a0.x, fmaf(hi.x, a1.y,  hi.y * a1.x)));
    a0 = make_float2(n0x, n0y); a1 = make_float2(n1x, n1y);
}

// ---------------------------------------------------------------------------
__global__ __launch_bounds__(512, 1)
void fused_kernel(const float* __restrict__ data,
                  const float* __restrict__ labels,
                  const float* __restrict__ params,
                  float* __restrict__ out)
{
    __shared__ float4 pool[2048];                 // 32 KB: transpose / gram staging+sbuf
    __shared__ ull    UmatU[NB * N_Q * 4];        // folded U (float view) / gram rbuf
    __shared__ float  crz[NB * N_Q];
    __shared__ float  tCZc[NB * 4], tCZs[NB * 4]; // CRZ odd-d delta sincos
    __shared__ float  red1[16], red2[16], red3[16];
    __shared__ unsigned s_epoch;
    __shared__ int    s_win;

    float* Umat = (float*)UmatU;

    const int t  = threadIdx.x;
    const int pt = blockIdx.x;

    // ownership transpose: swap t bits [8:5] <-> [3:0], keep bit 4
    const int swp  = (t & 0x10) | ((t & 0xF) << 5) | ((t >> 5) & 0xF);
    const int widx = t   ^ ((t   >> 5) & 0xF);
    const int ridx = swp ^ ((swp >> 5) & 0xF);
    const int dA0 = 2 * t;
    const int dB0 = 2 * swp;
    const int czA = (((dA0 >> 9) & 1) << 1) | ((dA0 >> 1) & 1);
    const int czB = (((dB0 >> 9) & 1) << 1) | ((dB0 >> 1) & 1);

    // ---- launch epoch (replay-safe: launches are stream-ordered) ----
    if (t == 0) s_epoch = atomicAdd(&g_launch, 1u) / NBLK;

    // ---- init: folded U matrices (per point) + CRZ tables ----
    if (t < NB * N_Q) {
        int b = t / N_Q, q = t % N_Q;
        float th    = data[pt * FEAT + b * N_Q + q];
        float theta = params[(b * 2 + 0) * N_Q + q];
        float c, s;   __sincosf(0.5f * theta, &s, &c);
        float st, ct; __sincosf(0.5f * th, &st, &ct);
        const float iv = 0.70710678118654752440f;
        float cps = (c + s) * iv, cms = (c - s) * iv;
        float* Up = &Umat[t * 8];
        Up[0] =  cms * ct; Up[1] = -cps * st;    // u00
        Up[2] =  cps * ct; Up[3] = -cms * st;    // u01
        Up[4] = -cms * ct; Up[5] = -cps * st;    // u11
        Up[6] =  cps * ct; Up[7] =  cms * st;    // u10
        crz[t] = params[(b * 2 + 1) * N_Q + q];
    }
    if (t >= 256 && t < 256 + NB * 4) {
        int u = t - 256, b = u >> 2, idx = u & 3;
        float cz9 = params[(b * 2 + 1) * N_Q + 9];
        float cz8 = params[(b * 2 + 1) * N_Q + 8];
        float delta = ((idx & 2) ? 0.5f : -0.5f) * cz9 + ((idx & 1) ? cz8 : 0.0f);
        float sn, cs; __sincosf(delta, &sn, &cs);
        tCZc[u] = cs; tCZs[u] = sn;
    }
    __syncthreads();
    const unsigned epoch = s_epoch;

    // ====================== PHASE 1: state prep ======================
    {
        float2 a0, a1;
        int tb = 0;

        auto crzApply = [&](int blk, int d0, int czidx) {
            float ang = 0.0f;
            #pragma unroll
            for (int q = 0; q < N_Q; q++) {
                int pA = N_Q - 1 - q;
                int pB = (q == N_Q - 1) ? (N_Q - 1) : (N_Q - 2 - q);
                if ((d0 >> pA) & 1)
                    ang += (((d0 >> pB) & 1) ? 0.5f : -0.5f) * crz[blk * N_Q + q];
            }
            float s0, c0; __sincosf(ang, &s0, &c0);
            float cD = tCZc[blk * 4 + czidx], sD = tCZs[blk * 4 + czidx];
            float s1 = s0 * cD + c0 * sD;
            float c1 = c0 * cD - s0 * sD;
            float2 n0 = make_float2(a0.x * c0 - a0.y * s0, a0.x * s0 + a0.y * c0);
            float2 n1 = make_float2(a1.x * c1 - a1.y * s1, a1.x * s1 + a1.y * c1);
            a0 = n0; a1 = n1;
        };

        auto transpose = [&]() {
            float4* buf = pool + tb * 512;
            buf[widx] = make_float4(a0.x, a0.y, a1.x, a1.y);
            __syncthreads();
            float4 v = buf[ridx];
            a0 = make_float2(v.x, v.y);
            a1 = make_float2(v.z, v.w);
            tb ^= 1;
        };

        auto oddPattern = [&](int blk) {                 // state A -> B
            const float* Ub = &Umat[blk * N_Q * 8];
            bflyLocal(a0, a1, Ub + 9 * 8);
            #pragma unroll
            for (int k = 0; k < 5; k++)
                bfly(a0, a1, 1 << k, Ub + (8 - k) * 8, (t >> k) & 1);
            transpose();
            #pragma unroll
            for (int k = 0; k < 4; k++)
                bfly(a0, a1, 1 << k, Ub + (3 - k) * 8, (t >> k) & 1);
            crzApply(blk, dB0, czB);
        };

        auto evenPattern = [&](int blk) {                // state B -> A
            const float* Ub = &Umat[blk * N_Q * 8];
            bflyLocal(a0, a1, Ub + 9 * 8);
            #pragma unroll
            for (int k = 0; k < 4; k++)
                bfly(a0, a1, 1 << k, Ub + (3 - k) * 8, (t >> k) & 1);
            bfly(a0, a1, 16, Ub + 4 * 8, (t >> 4) & 1);
            transpose();
            #pragma unroll
            for (int k = 0; k < 4; k++)
                bfly(a0, a1, 1 << k, Ub + (8 - k) * 8, (t >> k) & 1);
            crzApply(blk, dA0, czA);
        };

        // circuit block 0: product state directly in B ownership
        {
            float px = 1.0f, py = 0.0f;
            #pragma unroll
            for (int q = 0; q < 9; q++) {
                int bit = (dB0 >> (N_Q - 1 - q)) & 1;
                const float* Up = &Umat[q * 8] + (bit ? 6 : 0);
                float ux = Up[0], uy = Up[1];
                float nx = px * ux - py * uy;
                float ny = px * uy + py * ux;
                px = nx; py = ny;
            }
            const float* U9 = &Umat[9 * 8];
            a0 = make_float2(px * U9[0] - py * U9[1], px * U9[1] + py * U9[0]);
            a1 = make_float2(px * U9[6] - py * U9[7], px * U9[7] + py * U9[6]);
            crzApply(0, dB0, czB);
        }

        #pragma unroll
        for (int pr = 0; pr < 4; pr++) {
            evenPattern(2 * pr + 1);
            oddPattern(2 * pr + 2);
        }
        evenPattern(9);                                  // ends in A

        g_psi[pt * (DIM / 2) + t] = make_float4(a0.x, a0.y, a1.x, a1.y);
    }

    // publish: this point's group gains one arrival
    __threadfence();
    __syncthreads();
    if (t == 0) atomicAdd(&g_grp[pt >> 3], 1u);

    // ====================== PHASE 2: balanced symmetric Gram ======================
    {
        const int u_r  = t >> 6;          // staging row (0..7)
        const int u_dp = t & 63;          // staging dp-local
        const bool offdiag = (blockIdx.x < 120);

        int grp1, grp2;
        if (offdiag) {
            int I = 0, rem = blockIdx.x;
            while (rem >= 15 - I) { rem -= 15 - I; I++; }
            grp1 = I; grp2 = I + 1 + rem;
        } else {
            int v = blockIdx.x - 120;
            grp1 = 2 * v; grp2 = 2 * v + 1;
        }

        // wait only for the two needed point-groups
        if (t == 0) {
            const unsigned tgt = 8u * (epoch + 1u);
            unsigned c;
            do { asm volatile("ld.acquire.gpu.u32 %0, [%1];" : "=r"(c) : "l"(&g_grp[grp1])); } while (c < tgt);
            do { asm volatile("ld.acquire.gpu.u32 %0, [%1];" : "=r"(c) : "l"(&g_grp[grp2])); } while (c < tgt);
        }
        __syncthreads();
        __threadfence();

        // prologue: stage chunk 0
        float4 rA = __ldg(&g_psi[(grp1 * 8 + u_r) * (DIM / 2) + u_dp]);
        float4 rB = __ldg(&g_psi[(grp2 * 8 + u_r) * (DIM / 2) + u_dp]);
        __syncthreads();
        pool[      u_dp * 8 + (u_r ^ (u_dp & 7))] = rA;
        pool[512 + u_dp * 8 + (u_r ^ (u_dp & 7))] = rB;
        __syncthreads();

        float v1 = 0.0f, v2 = 0.0f;

        if (offdiag) {
            // ---------- 2x2 register tiling: 16 subtiles x 32 split-K ----------
            const int i2 = t & 3;
            const int j2 = (t >> 2) & 3;
            const int ks = t >> 4;                        // 0..31
            ull accp[2][2] = {{0,0},{0,0}};
            ull accm[2][2] = {{0,0},{0,0}};

            #pragma unroll
            for (int c = 0; c < 8; c++) {
                const float4* base = pool + (c & 1) * 1024;
                const float4* s1 = base;                  // grp1 rows (i)
                const float4* s2 = base + 512;            // grp2 rows (j)
                if (c < 7) {
                    rA = __ldg(&g_psi[(grp1 * 8 + u_r) * (DIM / 2) + (c + 1) * 64 + u_dp]);
                    rB = __ldg(&g_psi[(grp2 * 8 + u_r) * (DIM / 2) + (c + 1) * 64 + u_dp]);
                }
                #pragma unroll
                for (int it = 0; it < 2; it++) {
                    int dpl = ks * 2 + it;
                    int k0  = dpl & 7;
                    float4 A[2], B[2];
                    A[0] = s1[dpl * 8 + ((i2 * 2    ) ^ k0)];
                    A[1] = s1[dpl * 8 + ((i2 * 2 + 1) ^ k0)];
                    B[0] = s2[dpl * 8 + ((j2 * 2    ) ^ k0)];
                    B[1] = s2[dpl * 8 + ((j2 * 2 + 1) ^ k0)];
                    #pragma unroll
                    for (int a = 0; a < 2; a++)
                        #pragma unroll
                        for (int b = 0; b < 2; b++) {
                            fma2acc(accp[a][b], pk(A[a].x, A[a].y), pk(B[b].x, B[b].y));
                            fma2acc(accm[a][b], pk(A[a].x, A[a].y), pk(B[b].y, B[b].x));
                            fma2acc(accp[a][b], pk(A[a].z, A[a].w), pk(B[b].z, B[b].w));
                            fma2acc(accm[a][b], pk(A[a].z, A[a].w), pk(B[b].w, B[b].z));
                        }
                }
                if (c < 7) {
                    float4* dst = pool + ((c + 1) & 1) * 1024;
                    dst[      u_dp * 8 + (u_r ^ (u_dp & 7))] = rA;
                    dst[512 + u_dp * 8 + (u_r ^ (u_dp & 7))] = rB;
                }
                __syncthreads();
            }

            // stash per-thread 8 accumulators: sbuf[(ks*16+tile)*8 + k]
            ull* sbuf = (ull*)pool;
            const int tile = t & 15;
            #pragma unroll
            for (int a = 0; a < 2; a++)
                #pragma unroll
                for (int b = 0; b < 2; b++) {
                    sbuf[t * 8 + (a * 2 + b) * 2 + 0] = accp[a][b];
                    sbuf[t * 8 + (a * 2 + b) * 2 + 1] = accm[a][b];
                }
            __syncthreads();

            // parallel cross-ks reduction: 128 threads, one (tile, k) each
            ull* rbuf = UmatU;                            // Umat dead after prep
            if (t < 128) {
                int rt = t >> 3, k = t & 7;               // rt = tile, k = acc slot
                ull s = sbuf[(0 * 16 + rt) * 8 + k];
                #pragma unroll
                for (int g = 1; g < 32; g++)
                    add2acc(s, sbuf[(g * 16 + rt) * 8 + k]);
                rbuf[rt * 8 + k] = s;
            }
            __syncthreads();

            // 64 outputs: thread t<64 -> tile = t>>2, q = t&3
            if (t < 64) {
                int rt = t >> 2, q = t & 3;
                int ri2 = rt & 3, rj2 = rt >> 2;
                int a = q >> 1, b = q & 1;
                ull ap = rbuf[rt * 8 + q * 2 + 0];
                ull am = rbuf[rt * 8 + q * 2 + 1];
                float pxx, pyy, mxy, myx;
                upk(ap, pxx, pyy);
                upk(am, mxy, myx);
                float re = pxx + pyy;
                float im = myx - mxy;
                float K  = re * re + im * im;
                int gi = grp1 * 8 + ri2 * 2 + a;
                int gj = grp2 * 8 + rj2 * 2 + b;
                v1 = 2.0f * labels[gi] * labels[gj] * K;
                v2 = 2.0f * K * K;
            }
        } else {
            // ---------- diagonal pair block: old 1x1 path ----------
            int ii, jj, op;
            float w;
            {
                int slot = t & 63;
                if (slot < 56) {
                    int sel = (slot >= 28);
                    int p = slot - (sel ? 28 : 0);
                    int r = 0;
                    while (p >= 7 - r) { p -= 7 - r; r++; }
                    ii = r; jj = r + 1 + p;
                    op = sel; w = 2.0f;
                } else { ii = 0; jj = 0; op = 0; w = 0.0f; }
            }
            const int gi = (op ? grp2 : grp1) * 8 + ii;
            const int gj = (op ? grp2 : grp1) * 8 + jj;
            const int ks = t >> 6;

            ull accp = 0ull, accm = 0ull;
            #pragma unroll
            for (int c = 0; c < 8; c++) {
                const float4* base = pool + (c & 1) * 1024;
                const float4* s1 = base + op * 512;
                if (c < 7) {
                    rA = __ldg(&g_psi[(grp1 * 8 + u_r) * (DIM / 2) + (c + 1) * 64 + u_dp]);
                    rB = __ldg(&g_psi[(grp2 * 8 + u_r) * (DIM / 2) + (c + 1) * 64 + u_dp]);
                }
                #pragma unroll
                for (int it = 0; it < 8; it++) {
                    int dpl = ks * 8 + it;
                    int k0  = dpl & 7;
                    float4 A = s1[dpl * 8 + (ii ^ k0)];
                    float4 B = s1[dpl * 8 + (jj ^ k0)];
                    fma2acc(accp, pk(A.x, A.y), pk(B.x, B.y));
                    fma2acc(accm, pk(A.x, A.y), pk(B.y, B.x));
                    fma2acc(accp, pk(A.z, A.w), pk(B.z, B.w));
                    fma2acc(accm, pk(A.z, A.w), pk(B.w, B.z));
                }
                if (c < 7) {
                    float4* dst = pool + ((c + 1) & 1) * 1024;
                    dst[      u_dp * 8 + (u_r ^ (u_dp & 7))] = rA;
                    dst[512 + u_dp * 8 + (u_r ^ (u_dp & 7))] = rB;
                }
                __syncthreads();
            }

            ull* sbuf = (ull*)pool;
            sbuf[t * 2 + 0] = accp;
            sbuf[t * 2 + 1] = accm;
            __syncthreads();

            if (ks == 0) {
                #pragma unroll
                for (int g = 1; g < 8; g++) {
                    add2acc(accp, sbuf[(g * 64 + t) * 2 + 0]);
                    add2acc(accm, sbuf[(g * 64 + t) * 2 + 1]);
                }
                float pxx, pyy, mxy, myx;
                upk(accp, pxx, pyy);
                upk(accm, mxy, myx);
                float re = pxx + pyy;
                float im = myx - mxy;
                float K  = re * re + im * im;
                v1 = w * labels[gi] * labels[gj] * K;
                v2 = w * K * K;
            }
        }

        // block reduction of v1, v2
        #pragma unroll
        for (int o = 16; o; o >>= 1) {
            v1 += __shfl_down_sync(0xffffffffu, v1, o);
            v2 += __shfl_down_sync(0xffffffffu, v2, o);
        }
        const int warp = t >> 5, lanei = t & 31;
        if (lanei == 0) { red1[warp] = v1; red2[warp] = v2; }
        __syncthreads();
        if (t < 16) {
            v1 = red1[t]; v2 = red2[t];
            #pragma unroll
            for (int o = 8; o; o >>= 1) {
                v1 += __shfl_down_sync(0xffffu, v1, o);
                v2 += __shfl_down_sync(0xffffu, v2, o);
            }
            if (t == 0) {
                g_part[blockIdx.x * 2 + 0] = v1;
                g_part[blockIdx.x * 2 + 1] = v2;
            }
        }
    }

    // ====================== PHASE 3: last-block final ======================
    if (t == 0) {
        __threadfence();
        unsigned old = atomicAdd(&g_tick, 1u);
        s_win = ((old % NBLK) == (NBLK - 1)) ? 1 : 0;
    }
    __syncthreads();

    if (s_win) {
        __threadfence();
        volatile float* vp = (volatile float*)g_part;
        float pol = 0.0f, k2 = 0.0f, l2 = 0.0f;
        if (t < NBLK) { pol = vp[2 * t]; k2 = vp[2 * t + 1]; }
        if (t < P) {
            float l = labels[t];
            l2 = l * l;
            pol += l2;                      // analytic diagonal K[i,i]=1
            k2  += 1.0f;
        }
        #pragma unroll
        for (int o = 16; o; o >>= 1) {
            pol += __shfl_down_sync(0xffffffffu, pol, o);
            k2  += __shfl_down_sync(0xffffffffu, k2, o);
            l2  += __shfl_down_sync(0xffffffffu, l2, o);
        }
        const int warp = t >> 5, lanei = t & 31;
        if (lanei == 0) { red1[warp] = pol; red2[warp] = k2; red3[warp] = l2; }
        __syncthreads();
        if (t == 0) {
            float POL = 0.0f, K2 = 0.0f, SL = 0.0f;
            #pragma unroll
            for (int wv = 0; wv < 16; wv++) {
                POL += red1[wv]; K2 += red2[wv]; SL += red3[wv];
            }
            out[0] = POL / (sqrtf(K2) * SL);
        }
    }
}

// ---------------------------------------------------------------------------
extern "C" void kernel_launch(void* const* d_in, const int* in_sizes, int n_in,
                              void* d_out, int out_size)
{
    const float* data   = (const float*)d_in[0];   // [128, 100]
    const float* labels = (const float*)d_in[1];   // [128]
    const float* params = (const float*)d_in[2];   // [10, 2, 10]
    float* out = (float*)d_out;

    fused_kernel<<<NBLK, 512>>>(data, labels, params, out);
}